// round 12
// baseline (speedup 1.0000x reference)
#include <cuda_runtime.h>
#include <cstdint>

#define TOKENS 64
#define IN_F   4096
#define OUT_F  11008
#define RANK   16
#define BN     80
#define NITER2 64            // macro-iterations of K=64
#define NCTA   138           // ceil(11008/80)
#define NTHR   512           // 16 warps = 2 wn x 8 kg

// scratch
__device__ float g_tp[4 * TOKENS * RANK];               // k-quarter partials of t
__device__ float g_xfrag[128 * 16 * 32 * 4];            // 1 MB, tf32-hi x fragments

// ---------------------------------------------------------------------------
__device__ __forceinline__ uint32_t smem_u32(const void* p) {
    uint32_t a;
    asm("{ .reg .u64 t; cvta.to.shared.u64 t, %1; cvt.u32.u64 %0, t; }" : "=r"(a) : "l"(p));
    return a;
}
__device__ __forceinline__ void cp16(void* dst_smem, const void* src) {
    asm volatile("cp.async.cg.shared.global [%0], [%1], 16;"
                 :: "r"(smem_u32(dst_smem)), "l"(src));
}
__device__ __forceinline__ void mma_tf32(float* d, const uint32_t* a, const uint32_t* b) {
    asm volatile("mma.sync.aligned.m16n8k8.row.col.f32.tf32.tf32.f32 "
        "{%0,%1,%2,%3}, {%4,%5,%6,%7}, {%8,%9}, {%0,%1,%2,%3};"
        : "+f"(d[0]), "+f"(d[1]), "+f"(d[2]), "+f"(d[3])
        : "r"(a[0]), "r"(a[1]), "r"(a[2]), "r"(a[3]), "r"(b[0]), "r"(b[1]));
}
__device__ __forceinline__ float tf32_rn(float v) {
    uint32_t h;
    asm("cvt.rna.tf32.f32 %0, %1;" : "=r"(h) : "f"(v));
    return __uint_as_float(h);
}

// ---------------------------------------------------------------------------
// Prep kernel (512 blocks x 256 threads):
//   blocks [0,256):  pack x into tf32-hi m16n8k8 A-fragments (per 32-wide k)
//   blocks [256,512): t partials over K-quarters
// ---------------------------------------------------------------------------
__global__ void __launch_bounds__(256) prep_kernel(
    const float* __restrict__ x, const float* __restrict__ A)
{
    if (blockIdx.x < 256) {
        const int gid  = blockIdx.x * 256 + threadIdx.x;   // 65536
        const int lane = gid & 31;
        const int ks   = (gid >> 5) & 3;
        const int mt   = (gid >> 7) & 3;
        const int i    = gid >> 9;
        const int m    = mt * 16 + (lane >> 2);
        const int k    = i * 32 + ks * 8 + (lane & 3);

        const float h00 = tf32_rn(x[m * IN_F + k]);
        const float h01 = tf32_rn(x[m * IN_F + k + 4]);
        const float h10 = tf32_rn(x[(m + 8) * IN_F + k]);
        const float h11 = tf32_rn(x[(m + 8) * IN_F + k + 4]);

        const int slot = mt * 4 + ks;
        *(float4*)(g_xfrag + ((size_t)i * 16 + slot) * 128 + lane * 4) =
            make_float4(h00, h10, h01, h11);
    } else {
        const int b   = blockIdx.x - 256;
        const int m   = b >> 2, q = b & 3;
        const int tid = threadIdx.x;
        const int wid = tid >> 5, lane = tid & 31;
        const int k4  = q * 256 + tid;
        const float4 xv = ((const float4*)(x + (size_t)m * IN_F))[k4];
        const float4* A4 = (const float4*)A;

        float racc[RANK];
#pragma unroll
        for (int r = 0; r < RANK; r++) {
            const float4 av = A4[r * 1024 + k4];
            racc[r] = xv.x * av.x + xv.y * av.y + xv.z * av.z + xv.w * av.w;
        }
#pragma unroll
        for (int r = 0; r < RANK; r++)
#pragma unroll
            for (int o = 16; o; o >>= 1)
                racc[r] += __shfl_xor_sync(0xFFFFFFFFu, racc[r], o);

        __shared__ float sp[8][RANK];
        if (lane == 0)
#pragma unroll
            for (int r = 0; r < RANK; r++) sp[wid][r] = racc[r];
        __syncthreads();
        if (tid < RANK) {
            float s = 0.0f;
#pragma unroll
            for (int w = 0; w < 8; w++) s += sp[w][tid];
            g_tp[(q * TOKENS + m) * RANK + tid] = s;
        }
    }
}

// ---------------------------------------------------------------------------
// GEMM: single-pass tf32, W fed raw (HW truncation, bias-corrected via scale).
// CTA: 64 tok x 80 ch, grid 138 = one full wave. 16 warps = 2 wn x 8 kg,
// macro-iter K=64; each warp owns one k8 slice (traffic-neutral K split,
// 4 warps/SMSP for latency hiding). 4-stage cp.async pipeline of K64 stages.
// ---------------------------------------------------------------------------
#define XS_SUB   8192                  // x frags per K32 half
#define WS_SUB   11520                 // 80 rows * 36 floats * 4B per K32 half
#define XS_SZ    (2 * XS_SUB)          // 16384
#define STAGE_SZ (XS_SZ + 2 * WS_SUB)  // 39424
#define NSTAGE   4
#define OFF_T    (NSTAGE * STAGE_SZ)   // 157696
#define SMEM_SZ  (OFF_T + TOKENS * RANK * 4)   // 161792

__global__ void __launch_bounds__(NTHR, 1) qgemm_tf32(
    const float* __restrict__ W,     const float* __restrict__ scale,
    const float* __restrict__ Bl,    const float* __restrict__ bias,
    float* __restrict__ out)
{
    extern __shared__ char smem[];
    float* sT = (float*)(smem + OFF_T);
    const int tid  = threadIdx.x;
    const int n0   = blockIdx.x * BN;
    const int warp = tid >> 5, lane = tid & 31;
    const int wn = warp & 1, kg = warp >> 1;   // 2 n-warps x 8 k-groups
    const int khalf = kg >> 2, ks = kg & 3;    // K32 half, k8 slice in half
    const int g  = lane >> 2, j = lane & 3;

    float4 acc[4][5];                          // [mt][nt]
#pragma unroll
    for (int a = 0; a < 4; a++)
#pragma unroll
        for (int b = 0; b < 5; b++) acc[a][b] = make_float4(0.f, 0.f, 0.f, 0.f);

    // W loader: per K32 half, 80 rows x 8 quads = 640 chunks.
    // thread covers chunk tid (rows 0..63) and, for tid<128, chunk tid+512
    // (rows 64..79) — in BOTH halves. Rows clamped for the edge CTA.
    const int wrA = tid >> 3, wq = tid & 7;
    const int wrB = 64 + (tid >> 3);           // only used when tid < 128
    int rowA = n0 + wrA; if (rowA > OUT_F - 1) rowA = OUT_F - 1;
    int rowB = n0 + wrB; if (rowB > OUT_F - 1) rowB = OUT_F - 1;
    const float* wsrcA = W + (size_t)rowA * IN_F + wq * 4;
    const float* wsrcB = W + (size_t)rowB * IN_F + wq * 4;

#define ISSUE_STAGE(s) do {                                                     \
    if ((s) < NITER2) {                                                         \
        char* buf = smem + ((s) & 3) * STAGE_SZ;                                \
        const float* xsrc = g_xfrag + (size_t)(s) * 4096;                       \
        cp16(buf + tid * 16, xsrc + tid * 4);                                   \
        cp16(buf + (tid + 512) * 16, xsrc + (tid + 512) * 4);                   \
        cp16(buf + XS_SZ + wrA * 144 + wq * 16, wsrcA + (size_t)(s) * 64);      \
        cp16(buf + XS_SZ + WS_SUB + wrA * 144 + wq * 16,                        \
             wsrcA + (size_t)(s) * 64 + 32);                                    \
        if (tid < 128) {                                                        \
            cp16(buf + XS_SZ + wrB * 144 + wq * 16, wsrcB + (size_t)(s) * 64);  \
            cp16(buf + XS_SZ + WS_SUB + wrB * 144 + wq * 16,                    \
                 wsrcB + (size_t)(s) * 64 + 32);                                \
        }                                                                       \
    }                                                                           \
    asm volatile("cp.async.commit_group;" ::: "memory");                        \
} while (0)

    ISSUE_STAGE(0); ISSUE_STAGE(1); ISSUE_STAGE(2);

    // reduce t partials into smem (overlaps with in-flight loads)
    for (int e = tid; e < TOKENS * RANK; e += NTHR)
        sT[e] = g_tp[e] + g_tp[1024 + e] + g_tp[2048 + e] + g_tp[3072 + e];

#pragma unroll 1
    for (int i = 0; i < NITER2; i++) {
        asm volatile("cp.async.wait_group 2;" ::: "memory");
        __syncthreads();
        const char* buf = smem + (i & 3) * STAGE_SZ;
        const uint32_t* xs = (const uint32_t*)(buf + khalf * XS_SUB);
        const uint32_t* ws = (const uint32_t*)(buf + XS_SZ + khalf * WS_SUB)
                             + (wn * 40 + g) * 36 + ks * 8 + j;

        uint32_t a[4][4];
#pragma unroll
        for (int mt = 0; mt < 4; mt++) {
            const uint4 v = *(const uint4*)(xs + (mt * 4 + ks) * 128 + lane * 4);
            a[mt][0] = v.x; a[mt][1] = v.y; a[mt][2] = v.z; a[mt][3] = v.w;
        }
        uint32_t b[5][2];
#pragma unroll
        for (int nt = 0; nt < 5; nt++) {
            b[nt][0] = ws[nt * 288];
            b[nt][1] = ws[nt * 288 + 4];
        }

        // issue next stage between frag loads and MMAs: LSU work overlaps the
        // LDS->MMA latency window. Writes buf (i+3)&3 = (i-1)&3, fenced by
        // the barrier above (all warps completed iter i-1 reads).
        ISSUE_STAGE(i + 3);

#pragma unroll
        for (int mt = 0; mt < 4; mt++)
#pragma unroll
            for (int nt = 0; nt < 5; nt++)
                mma_tf32((float*)&acc[mt][nt], a[mt], b[nt]);
    }
    __syncthreads();   // all stage-buffer reads done; reuse smem as reduce area

    // ---- 8-way K reduction: pairwise pass, then the proven 4-way scheme ---
    float* red = (float*)smem;
    // phase 1: kg in 4..7 publish
    if (kg >= 4) {
#pragma unroll
        for (int nt = 0; nt < 5; nt++)
#pragma unroll
            for (int mt = 0; mt < 4; mt++) {
                const int slot = ((nt * 4 + (kg - 4)) * 2 + wn) * 4 + mt;
                *(float4*)(red + slot * 128 + lane * 4) = acc[mt][nt];
            }
    }
    __syncthreads();
    if (kg < 4) {
#pragma unroll
        for (int nt = 0; nt < 5; nt++)
#pragma unroll
            for (int mt = 0; mt < 4; mt++) {
                const int slot = ((nt * 4 + kg) * 2 + wn) * 4 + mt;
                const float4 v = *(const float4*)(red + slot * 128 + lane * 4);
                acc[mt][nt].x += v.x; acc[mt][nt].y += v.y;
                acc[mt][nt].z += v.z; acc[mt][nt].w += v.w;
            }
    }
    __syncthreads();
    // phase 2: 4-way among kg<4
    if (kg < 4) {
#pragma unroll
        for (int nt = 0; nt < 5; nt++)
#pragma unroll
            for (int mt = 0; mt < 4; mt++) {
                const int slot = ((nt * 4 + kg) * 2 + wn) * 4 + mt;
                *(float4*)(red + slot * 128 + lane * 4) = acc[mt][nt];
            }
    }
    __syncthreads();

    if (kg < 4) {
        // warp (wn,kg) owns nt = kg; warp kg==0 also owns nt = 4
#pragma unroll
        for (int own = 0; own < 2; own++) {
            const int nt = (own == 0) ? kg : 4;
            if (own == 1 && kg != 0) break;

            float4 f[4];
#pragma unroll
            for (int mt = 0; mt < 4; mt++) f[mt] = make_float4(0.f, 0.f, 0.f, 0.f);
#pragma unroll
            for (int src = 0; src < 4; src++)
#pragma unroll
                for (int mt = 0; mt < 4; mt++) {
                    const int slot = ((nt * 4 + src) * 2 + wn) * 4 + mt;
                    const float4 v = *(const float4*)(red + slot * 128 + lane * 4);
                    f[mt].x += v.x; f[mt].y += v.y; f[mt].z += v.z; f[mt].w += v.w;
                }

            const float corr = 1.00048828125f;   // 1 + 2^-11 tf32 bias fix
            const int ch = n0 + wn * 40 + nt * 8 + 2 * j;
            if (ch < OUT_F) {
                const float2 sc = *(const float2*)(scale + ch);
                const float2 bi = *(const float2*)(bias + ch);
                const float s0 = sc.x * corr, s1 = sc.y * corr;
                const float4* bl0 = (const float4*)(Bl + (size_t)ch * RANK);
                const float4* bl1 = (const float4*)(Bl + (size_t)(ch + 1) * RANK);
                float4 b0[4], b1[4];
#pragma unroll
                for (int q = 0; q < 4; q++) { b0[q] = bl0[q]; b1[q] = bl1[q]; }

#pragma unroll
                for (int mt = 0; mt < 4; mt++) {
                    const int tokA = mt * 16 + g;
                    const int tokB = tokA + 8;
                    float l0 = 0.f, l1 = 0.f, l0b = 0.f, l1b = 0.f;
#pragma unroll
                    for (int q = 0; q < 4; q++) {
                        const float4 ta = ((const float4*)(sT + tokA * RANK))[q];
                        const float4 tb = ((const float4*)(sT + tokB * RANK))[q];
                        l0  += ta.x * b0[q].x + ta.y * b0[q].y + ta.z * b0[q].z + ta.w * b0[q].w;
                        l1  += ta.x * b1[q].x + ta.y * b1[q].y + ta.z * b1[q].z + ta.w * b1[q].w;
                        l0b += tb.x * b0[q].x + tb.y * b0[q].y + tb.z * b0[q].z + tb.w * b0[q].w;
                        l1b += tb.x * b1[q].x + tb.y * b1[q].y + tb.z * b1[q].z + tb.w * b1[q].w;
                    }
                    *(float2*)(out + (size_t)tokA * OUT_F + ch) =
                        make_float2(f[mt].x * s0 + l0 + bi.x, f[mt].y * s1 + l1 + bi.y);
                    *(float2*)(out + (size_t)tokB * OUT_F + ch) =
                        make_float2(f[mt].z * s0 + l0b + bi.x, f[mt].w * s1 + l1b + bi.y);
                }
            }
        }
    }
}

// ---------------------------------------------------------------------------
extern "C" void kernel_launch(void* const* d_in, const int* in_sizes, int n_in,
                              void* d_out, int out_size)
{
    const float* x     = (const float*)d_in[0];
    const float* W     = (const float*)d_in[1];
    const float* scale = (const float*)d_in[2];
    const float* A     = (const float*)d_in[3];
    const float* B     = (const float*)d_in[4];
    const float* bias  = (const float*)d_in[5];
    float* out = (float*)d_out;

    cudaFuncSetAttribute(qgemm_tf32, cudaFuncAttributeMaxDynamicSharedMemorySize, SMEM_SZ);
    prep_kernel<<<512, 256>>>(x, A);
    qgemm_tf32<<<NCTA, NTHR, SMEM_SZ>>>(W, scale, B, bias, out);
}

// round 13
// speedup vs baseline: 1.0349x; 1.0349x over previous
#include <cuda_runtime.h>
#include <cstdint>

#define TOKENS 64
#define IN_F   4096
#define OUT_F  11008
#define RANK   16
#define BN     80
#define BK     32
#define NITER  (IN_F / BK)   // 128
#define NCTA   138           // ceil(11008/80)
#define NTHR   512           // 16 warps = 2 wn x 2 mh x 4 kg

// scratch
__device__ float g_tp[4 * TOKENS * RANK];               // k-quarter partials of t
__device__ float g_xfrag[NITER * 16 * 32 * 4];          // 1 MB, tf32-hi x fragments

// ---------------------------------------------------------------------------
__device__ __forceinline__ uint32_t smem_u32(const void* p) {
    uint32_t a;
    asm("{ .reg .u64 t; cvta.to.shared.u64 t, %1; cvt.u32.u64 %0, t; }" : "=r"(a) : "l"(p));
    return a;
}
__device__ __forceinline__ void cp16(void* dst_smem, const void* src) {
    asm volatile("cp.async.cg.shared.global [%0], [%1], 16;"
                 :: "r"(smem_u32(dst_smem)), "l"(src));
}
__device__ __forceinline__ void mma_tf32(float* d, const uint32_t* a, const uint32_t* b) {
    asm volatile("mma.sync.aligned.m16n8k8.row.col.f32.tf32.tf32.f32 "
        "{%0,%1,%2,%3}, {%4,%5,%6,%7}, {%8,%9}, {%0,%1,%2,%3};"
        : "+f"(d[0]), "+f"(d[1]), "+f"(d[2]), "+f"(d[3])
        : "r"(a[0]), "r"(a[1]), "r"(a[2]), "r"(a[3]), "r"(b[0]), "r"(b[1]));
}
__device__ __forceinline__ float tf32_rn(float v) {
    uint32_t h;
    asm("cvt.rna.tf32.f32 %0, %1;" : "=r"(h) : "f"(v));
    return __uint_as_float(h);
}

// ---------------------------------------------------------------------------
// Prep kernel (512 blocks x 256 threads):
//   blocks [0,256):  pack x into tf32-hi m16n8k8 A-fragments (per 32-wide k)
//   blocks [256,512): t partials over K-quarters
// ---------------------------------------------------------------------------
__global__ void __launch_bounds__(256) prep_kernel(
    const float* __restrict__ x, const float* __restrict__ A)
{
    if (blockIdx.x < 256) {
        const int gid  = blockIdx.x * 256 + threadIdx.x;   // 65536
        const int lane = gid & 31;
        const int ks   = (gid >> 5) & 3;
        const int mt   = (gid >> 7) & 3;
        const int i    = gid >> 9;
        const int m    = mt * 16 + (lane >> 2);
        const int k    = i * BK + ks * 8 + (lane & 3);

        const float h00 = tf32_rn(x[m * IN_F + k]);
        const float h01 = tf32_rn(x[m * IN_F + k + 4]);
        const float h10 = tf32_rn(x[(m + 8) * IN_F + k]);
        const float h11 = tf32_rn(x[(m + 8) * IN_F + k + 4]);

        const int slot = mt * 4 + ks;
        *(float4*)(g_xfrag + ((size_t)i * 16 + slot) * 128 + lane * 4) =
            make_float4(h00, h10, h01, h11);
    } else {
        const int b   = blockIdx.x - 256;
        const int m   = b >> 2, q = b & 3;
        const int tid = threadIdx.x;
        const int wid = tid >> 5, lane = tid & 31;
        const int k4  = q * 256 + tid;
        const float4 xv = ((const float4*)(x + (size_t)m * IN_F))[k4];
        const float4* A4 = (const float4*)A;

        float racc[RANK];
#pragma unroll
        for (int r = 0; r < RANK; r++) {
            const float4 av = A4[r * 1024 + k4];
            racc[r] = xv.x * av.x + xv.y * av.y + xv.z * av.z + xv.w * av.w;
        }
#pragma unroll
        for (int r = 0; r < RANK; r++)
#pragma unroll
            for (int o = 16; o; o >>= 1)
                racc[r] += __shfl_xor_sync(0xFFFFFFFFu, racc[r], o);

        __shared__ float sp[8][RANK];
        if (lane == 0)
#pragma unroll
            for (int r = 0; r < RANK; r++) sp[wid][r] = racc[r];
        __syncthreads();
        if (tid < RANK) {
            float s = 0.0f;
#pragma unroll
            for (int w = 0; w < 8; w++) s += sp[w][tid];
            g_tp[(q * TOKENS + m) * RANK + tid] = s;
        }
    }
}

// ---------------------------------------------------------------------------
// GEMM: single-pass tf32, W fed raw (HW truncation, bias-corrected via scale).
// CTA: 64 tok x 80 ch, grid 138 = one full wave. 16 warps = 2wn x 2mh x 4kg,
// warp tile 32 tok x 40 ch x k8: acc[2][5] = 40 regs/thread (no spills),
// 4 warps/SMSP. 8-stage cp.async pipeline, one __syncthreads per iteration.
// ---------------------------------------------------------------------------
#define XS_SZ    8192                  // 16 slots * 128 floats
#define WS_SZ    11520                 // 80 rows * 36 floats * 4B
#define STAGE_SZ (XS_SZ + WS_SZ)       // 19712
#define NSTAGE   8
#define OFF_T    (NSTAGE * STAGE_SZ)   // 157696
#define SMEM_SZ  (OFF_T + TOKENS * RANK * 4)   // 161792

__global__ void __launch_bounds__(NTHR, 1) qgemm_tf32(
    const float* __restrict__ W,     const float* __restrict__ scale,
    const float* __restrict__ Bl,    const float* __restrict__ bias,
    float* __restrict__ out)
{
    extern __shared__ char smem[];
    float* sT = (float*)(smem + OFF_T);
    const int tid  = threadIdx.x;
    const int n0   = blockIdx.x * BN;
    const int warp = tid >> 5, lane = tid & 31;
    const int wn = warp & 1;                   // n half
    const int mh = (warp >> 1) & 1;            // m half (2 mt groups each)
    const int kg = warp >> 2;                  // k8 slice 0..3
    const int g  = lane >> 2, j = lane & 3;

    float4 acc[2][5];                          // [mtl][nt] — 40 regs
#pragma unroll
    for (int a = 0; a < 2; a++)
#pragma unroll
        for (int b = 0; b < 5; b++) acc[a][b] = make_float4(0.f, 0.f, 0.f, 0.f);

    // W loader: 80 rows x 8 quads = 640 chunks; thread covers chunk tid
    // (rows 0..63), and (tid<128) chunk tid+512 (rows 64..79). Rows clamped.
    const int wrA = tid >> 3, wq = tid & 7;
    const int wrB = 64 + (tid >> 3);           // only used when tid < 128
    int rowA = n0 + wrA; if (rowA > OUT_F - 1) rowA = OUT_F - 1;
    int rowB = n0 + wrB; if (rowB > OUT_F - 1) rowB = OUT_F - 1;
    const float* wsrcA = W + (size_t)rowA * IN_F + wq * 4;
    const float* wsrcB = W + (size_t)rowB * IN_F + wq * 4;

#define ISSUE_STAGE(s) do {                                                     \
    if ((s) < NITER) {                                                          \
        char* buf = smem + ((s) & 7) * STAGE_SZ;                                \
        cp16(buf + tid * 16, g_xfrag + (size_t)(s) * 2048 + tid * 4);           \
        cp16(buf + XS_SZ + wrA * 144 + wq * 16, wsrcA + (size_t)(s) * BK);      \
        if (tid < 128)                                                          \
            cp16(buf + XS_SZ + wrB * 144 + wq * 16,                             \
                 wsrcB + (size_t)(s) * BK);                                     \
    }                                                                           \
    asm volatile("cp.async.commit_group;" ::: "memory");                        \
} while (0)

    ISSUE_STAGE(0); ISSUE_STAGE(1); ISSUE_STAGE(2); ISSUE_STAGE(3);
    ISSUE_STAGE(4); ISSUE_STAGE(5); ISSUE_STAGE(6);

    // reduce t partials into smem (overlaps with in-flight loads)
    for (int e = tid; e < TOKENS * RANK; e += NTHR)
        sT[e] = g_tp[e] + g_tp[1024 + e] + g_tp[2048 + e] + g_tp[3072 + e];

#pragma unroll 1
    for (int i = 0; i < NITER; i++) {
        asm volatile("cp.async.wait_group 6;" ::: "memory");
        __syncthreads();
        const char* buf = smem + (i & 7) * STAGE_SZ;
        const uint32_t* xs = (const uint32_t*)buf;
        const uint32_t* ws = (const uint32_t*)(buf + XS_SZ)
                             + (wn * 40 + g) * 36 + kg * 8 + j;

        uint32_t a[2][4];
#pragma unroll
        for (int mtl = 0; mtl < 2; mtl++) {
            const int mt = mh * 2 + mtl;
            const uint4 v = *(const uint4*)(xs + (mt * 4 + kg) * 128 + lane * 4);
            a[mtl][0] = v.x; a[mtl][1] = v.y; a[mtl][2] = v.z; a[mtl][3] = v.w;
        }
        uint32_t b[5][2];
#pragma unroll
        for (int nt = 0; nt < 5; nt++) {
            b[nt][0] = ws[nt * 288];
            b[nt][1] = ws[nt * 288 + 4];
        }

        // issue next stage between frag loads and MMAs: LSU overlaps the
        // LDS->MMA latency window. Writes buf (i+7)&7 = (i-1)&7, fenced by
        // the barrier above (all warps completed iter i-1 reads).
        ISSUE_STAGE(i + 7);

#pragma unroll
        for (int mtl = 0; mtl < 2; mtl++)
#pragma unroll
            for (int nt = 0; nt < 5; nt++)
                mma_tf32((float*)&acc[mtl][nt], a[mtl], b[nt]);
    }
    __syncthreads();   // all stage-buffer reads done; reuse smem as reduce area

    // ---- 4-way K reduction through smem (mh needs none: distinct rows) ----
    // slots: [nt(5)][kg(4)][wn(2)][mh(2)][mtl(2)] x 128 floats = 80 KB
    float* red = (float*)smem;
#pragma unroll
    for (int nt = 0; nt < 5; nt++)
#pragma unroll
        for (int mtl = 0; mtl < 2; mtl++) {
            const int slot = ((((nt * 4 + kg) * 2 + wn) * 2 + mh) * 2) + mtl;
            *(float4*)(red + slot * 128 + lane * 4) = acc[mtl][nt];
        }
    __syncthreads();

    // warp (wn,mh,kg) owns nt = kg (and nt = 4 when kg == 0), rows mh*32..+31
#pragma unroll
    for (int own = 0; own < 2; own++) {
        const int nt = (own == 0) ? kg : 4;
        if (own == 1 && kg != 0) break;

        float4 f[2];
#pragma unroll
        for (int mtl = 0; mtl < 2; mtl++) f[mtl] = make_float4(0.f, 0.f, 0.f, 0.f);
#pragma unroll
        for (int src = 0; src < 4; src++)
#pragma unroll
            for (int mtl = 0; mtl < 2; mtl++) {
                const int slot = ((((nt * 4 + src) * 2 + wn) * 2 + mh) * 2) + mtl;
                const float4 v = *(const float4*)(red + slot * 128 + lane * 4);
                f[mtl].x += v.x; f[mtl].y += v.y; f[mtl].z += v.z; f[mtl].w += v.w;
            }

        const float corr = 1.00048828125f;   // 1 + 2^-11 tf32-truncation fix
        const int ch = n0 + wn * 40 + nt * 8 + 2 * j;
        if (ch < OUT_F) {
            const float2 sc = *(const float2*)(scale + ch);
            const float2 bi = *(const float2*)(bias + ch);
            const float s0 = sc.x * corr, s1 = sc.y * corr;
            const float4* bl0 = (const float4*)(Bl + (size_t)ch * RANK);
            const float4* bl1 = (const float4*)(Bl + (size_t)(ch + 1) * RANK);
            float4 b0[4], b1[4];
#pragma unroll
            for (int q = 0; q < 4; q++) { b0[q] = bl0[q]; b1[q] = bl1[q]; }

#pragma unroll
            for (int mtl = 0; mtl < 2; mtl++) {
                const int mt = mh * 2 + mtl;
                const int tokA = mt * 16 + g;
                const int tokB = tokA + 8;
                float l0 = 0.f, l1 = 0.f, l0b = 0.f, l1b = 0.f;
#pragma unroll
                for (int q = 0; q < 4; q++) {
                    const float4 ta = ((const float4*)(sT + tokA * RANK))[q];
                    const float4 tb = ((const float4*)(sT + tokB * RANK))[q];
                    l0  += ta.x * b0[q].x + ta.y * b0[q].y + ta.z * b0[q].z + ta.w * b0[q].w;
                    l1  += ta.x * b1[q].x + ta.y * b1[q].y + ta.z * b1[q].z + ta.w * b1[q].w;
                    l0b += tb.x * b0[q].x + tb.y * b0[q].y + tb.z * b0[q].z + tb.w * b0[q].w;
                    l1b += tb.x * b1[q].x + tb.y * b1[q].y + tb.z * b1[q].z + tb.w * b1[q].w;
                }
                *(float2*)(out + (size_t)tokA * OUT_F + ch) =
                    make_float2(f[mtl].x * s0 + l0 + bi.x, f[mtl].y * s1 + l1 + bi.y);
                *(float2*)(out + (size_t)tokB * OUT_F + ch) =
                    make_float2(f[mtl].z * s0 + l0b + bi.x, f[mtl].w * s1 + l1b + bi.y);
            }
        }
    }
}

// ---------------------------------------------------------------------------
extern "C" void kernel_launch(void* const* d_in, const int* in_sizes, int n_in,
                              void* d_out, int out_size)
{
    const float* x     = (const float*)d_in[0];
    const float* W     = (const float*)d_in[1];
    const float* scale = (const float*)d_in[2];
    const float* A     = (const float*)d_in[3];
    const float* B     = (const float*)d_in[4];
    const float* bias  = (const float*)d_in[5];
    float* out = (float*)d_out;

    cudaFuncSetAttribute(qgemm_tf32, cudaFuncAttributeMaxDynamicSharedMemorySize, SMEM_SZ);
    prep_kernel<<<512, 256>>>(x, A);
    qgemm_tf32<<<NCTA, NTHR, SMEM_SZ>>>(W, scale, B, bias, out);
}

// round 14
// speedup vs baseline: 1.3212x; 1.2766x over previous
#include <cuda_runtime.h>
#include <cstdint>

#define TOKENS 64
#define IN_F   4096
#define OUT_F  11008
#define RANK   16
#define BN     80
#define BK     32
#define NITER  (IN_F / BK)   // 128
#define NCTA   138           // ceil(11008/80)
#define NTHR   256           // 8 warps = 2 wn x 4 kg

// scratch
__device__ float g_tp[4 * TOKENS * RANK];               // k-quarter partials of t
__device__ float g_xfrag[NITER * 16 * 32 * 4];          // 1 MB, tf32-hi x fragments

// ---------------------------------------------------------------------------
__device__ __forceinline__ uint32_t smem_u32(const void* p) {
    uint32_t a;
    asm("{ .reg .u64 t; cvta.to.shared.u64 t, %1; cvt.u32.u64 %0, t; }" : "=r"(a) : "l"(p));
    return a;
}
__device__ __forceinline__ void cp16(void* dst_smem, const void* src) {
    asm volatile("cp.async.cg.shared.global [%0], [%1], 16;"
                 :: "r"(smem_u32(dst_smem)), "l"(src));
}
__device__ __forceinline__ void mma_tf32(float* d, const uint32_t* a, const uint32_t* b) {
    asm volatile("mma.sync.aligned.m16n8k8.row.col.f32.tf32.tf32.f32 "
        "{%0,%1,%2,%3}, {%4,%5,%6,%7}, {%8,%9}, {%0,%1,%2,%3};"
        : "+f"(d[0]), "+f"(d[1]), "+f"(d[2]), "+f"(d[3])
        : "r"(a[0]), "r"(a[1]), "r"(a[2]), "r"(a[3]), "r"(b[0]), "r"(b[1]));
}
__device__ __forceinline__ float tf32_rn(float v) {
    uint32_t h;
    asm("cvt.rna.tf32.f32 %0, %1;" : "=r"(h) : "f"(v));
    return __uint_as_float(h);
}

// ---------------------------------------------------------------------------
// Prep kernel (512 blocks x 256 threads):
//   blocks [0,256):  pack x into tf32-hi m16n8k8 A-fragments (per 32-wide k)
//   blocks [256,512): t partials over K-quarters
// ---------------------------------------------------------------------------
__global__ void __launch_bounds__(256) prep_kernel(
    const float* __restrict__ x, const float* __restrict__ A)
{
    if (blockIdx.x < 256) {
        const int gid  = blockIdx.x * 256 + threadIdx.x;   // 65536
        const int lane = gid & 31;
        const int ks   = (gid >> 5) & 3;
        const int mt   = (gid >> 7) & 3;
        const int i    = gid >> 9;
        const int m    = mt * 16 + (lane >> 2);
        const int k    = i * BK + ks * 8 + (lane & 3);

        const float h00 = tf32_rn(x[m * IN_F + k]);
        const float h01 = tf32_rn(x[m * IN_F + k + 4]);
        const float h10 = tf32_rn(x[(m + 8) * IN_F + k]);
        const float h11 = tf32_rn(x[(m + 8) * IN_F + k + 4]);

        const int slot = mt * 4 + ks;
        *(float4*)(g_xfrag + ((size_t)i * 16 + slot) * 128 + lane * 4) =
            make_float4(h00, h10, h01, h11);
    } else {
        const int b   = blockIdx.x - 256;
        const int m   = b >> 2, q = b & 3;
        const int tid = threadIdx.x;
        const int wid = tid >> 5, lane = tid & 31;
        const int k4  = q * 256 + tid;
        const float4 xv = ((const float4*)(x + (size_t)m * IN_F))[k4];
        const float4* A4 = (const float4*)A;

        float racc[RANK];
#pragma unroll
        for (int r = 0; r < RANK; r++) {
            const float4 av = A4[r * 1024 + k4];
            racc[r] = xv.x * av.x + xv.y * av.y + xv.z * av.z + xv.w * av.w;
        }
#pragma unroll
        for (int r = 0; r < RANK; r++)
#pragma unroll
            for (int o = 16; o; o >>= 1)
                racc[r] += __shfl_xor_sync(0xFFFFFFFFu, racc[r], o);

        __shared__ float sp[8][RANK];
        if (lane == 0)
#pragma unroll
            for (int r = 0; r < RANK; r++) sp[wid][r] = racc[r];
        __syncthreads();
        if (tid < RANK) {
            float s = 0.0f;
#pragma unroll
            for (int w = 0; w < 8; w++) s += sp[w][tid];
            g_tp[(q * TOKENS + m) * RANK + tid] = s;
        }
    }
}

// ---------------------------------------------------------------------------
// GEMM: single-pass tf32, W fed raw (HW truncation, bias-corrected via scale).
// CTA: 64 tok x 80 ch, grid 138, 8 warps = 2 wn x 4 kg (R11 base config).
// NEW: register-level fragment pipeline — iter i+1's fragments are LDS'd
// into a second register set BEFORE iter i's MMAs, overlapping the smem
// burst with the tensor burst. Loop unrolled x2 for static ping-pong regs.
// ---------------------------------------------------------------------------
#define XS_SZ    8192                  // 16 slots * 128 floats
#define WS_SZ    11520                 // 80 rows * 36 floats * 4B
#define STAGE_SZ (XS_SZ + WS_SZ)       // 19712
#define NSTAGE   8
#define OFF_T    (NSTAGE * STAGE_SZ)   // 157696
#define SMEM_SZ  (OFF_T + TOKENS * RANK * 4)   // 161792

__global__ void __launch_bounds__(NTHR, 1) qgemm_tf32(
    const float* __restrict__ W,     const float* __restrict__ scale,
    const float* __restrict__ Bl,    const float* __restrict__ bias,
    float* __restrict__ out)
{
    extern __shared__ char smem[];
    float* sT = (float*)(smem + OFF_T);
    const int tid  = threadIdx.x;
    const int n0   = blockIdx.x * BN;
    const int warp = tid >> 5, lane = tid & 31;
    const int wn = warp & 1, kg = warp >> 1;   // 2 n-warps x 4 k-groups
    const int g  = lane >> 2, j = lane & 3;
    const int fragoff = (wn * 40 + g) * 36 + kg * 8 + j;

    float4 acc[4][5];                          // [mt][nt]
#pragma unroll
    for (int a = 0; a < 4; a++)
#pragma unroll
        for (int b = 0; b < 5; b++) acc[a][b] = make_float4(0.f, 0.f, 0.f, 0.f);

    // W loader: 80 rows x 8 quads = 640 chunks; thread covers chunks
    // tid, tid+256, and (tid<128) tid+512 — rows clamped for the edge CTA.
    const int wr0 = tid >> 3,         wq0 = tid & 7;
    const int wr1 = (tid + 256) >> 3, wq1 = tid & 7;
    const int wr2 = (tid + 512) >> 3, wq2 = tid & 7;
    int row0 = n0 + wr0; if (row0 > OUT_F - 1) row0 = OUT_F - 1;
    int row1 = n0 + wr1; if (row1 > OUT_F - 1) row1 = OUT_F - 1;
    int row2 = n0 + wr2; if (row2 > OUT_F - 1) row2 = OUT_F - 1;
    const float* wsrc0 = W + (size_t)row0 * IN_F + wq0 * 4;
    const float* wsrc1 = W + (size_t)row1 * IN_F + wq1 * 4;
    const float* wsrc2 = W + (size_t)row2 * IN_F + wq2 * 4;

#define ISSUE_STAGE(s) do {                                                     \
    if ((s) < NITER) {                                                          \
        char* buf = smem + ((s) & 7) * STAGE_SZ;                                \
        const float* xsrc = g_xfrag + (size_t)(s) * 2048;                       \
        cp16(buf + tid * 16, xsrc + tid * 4);                                   \
        cp16(buf + (tid + 256) * 16, xsrc + (tid + 256) * 4);                   \
        cp16(buf + XS_SZ + wr0 * 144 + wq0 * 16, wsrc0 + (size_t)(s) * BK);     \
        cp16(buf + XS_SZ + wr1 * 144 + wq1 * 16, wsrc1 + (size_t)(s) * BK);     \
        if (tid < 128)                                                          \
            cp16(buf + XS_SZ + wr2 * 144 + wq2 * 16,                            \
                 wsrc2 + (size_t)(s) * BK);                                     \
    }                                                                           \
    asm volatile("cp.async.commit_group;" ::: "memory");                        \
} while (0)

// Load one iteration's fragments (stage buffer -> registers)
#define LOAD_FRAGS(aR, bR, stg) do {                                            \
    const char* _buf = smem + ((stg) & 7) * STAGE_SZ;                           \
    const uint32_t* _xs = (const uint32_t*)_buf;                                \
    const uint32_t* _ws = (const uint32_t*)(_buf + XS_SZ) + fragoff;            \
    _Pragma("unroll")                                                           \
    for (int mt = 0; mt < 4; mt++)                                              \
        (aR)[mt] = *(const uint4*)(_xs + (mt * 4 + kg) * 128 + lane * 4);       \
    _Pragma("unroll")                                                           \
    for (int nt = 0; nt < 5; nt++) {                                            \
        (bR)[nt][0] = _ws[nt * 288];                                            \
        (bR)[nt][1] = _ws[nt * 288 + 4];                                        \
    }                                                                           \
} while (0)

#define DO_MMAS(aR, bR) do {                                                    \
    _Pragma("unroll")                                                           \
    for (int mt = 0; mt < 4; mt++)                                              \
        _Pragma("unroll")                                                       \
        for (int nt = 0; nt < 5; nt++)                                          \
            mma_tf32((float*)&acc[mt][nt], (const uint32_t*)&(aR)[mt],          \
                     (bR)[nt]);                                                 \
} while (0)

    ISSUE_STAGE(0); ISSUE_STAGE(1); ISSUE_STAGE(2); ISSUE_STAGE(3);
    ISSUE_STAGE(4); ISSUE_STAGE(5); ISSUE_STAGE(6);

    // reduce t partials into smem (overlaps with in-flight loads)
    for (int e = tid; e < TOKENS * RANK; e += NTHR)
        sT[e] = g_tp[e] + g_tp[1024 + e] + g_tp[2048 + e] + g_tp[3072 + e];

    uint4    a0[4], a1[4];
    uint32_t b0[5][2], b1[5][2];

    // prologue: stage 0 complete (7 groups issued, wait 6), load frags(0)
    asm volatile("cp.async.wait_group 6;" ::: "memory");
    __syncthreads();
    LOAD_FRAGS(a0, b0, 0);

#pragma unroll 1
    for (int i = 0; i < NITER; i += 2) {
        // --- iter i: prefetch frags(i+1), MMA frags(i) -----------------
        asm volatile("cp.async.wait_group 5;" ::: "memory");
        __syncthreads();                       // stages <= i+1 visible CTA-wide
        LOAD_FRAGS(a1, b1, i + 1);
        ISSUE_STAGE(i + 7);                    // writes buf (i-1)&7, fenced
        DO_MMAS(a0, b0);

        // --- iter i+1: prefetch frags(i+2), MMA frags(i+1) -------------
        asm volatile("cp.async.wait_group 5;" ::: "memory");
        __syncthreads();                       // stages <= i+2 visible
        if (i + 2 < NITER) LOAD_FRAGS(a0, b0, i + 2);
        ISSUE_STAGE(i + 8);
        DO_MMAS(a1, b1);
    }
    __syncthreads();   // all stage-buffer reads done; reuse smem as reduce area

    // ---- 4-way K reduction through smem: conflict-free slot layout --------
    float* red = (float*)smem;
#pragma unroll
    for (int nt = 0; nt < 5; nt++)
#pragma unroll
        for (int mt = 0; mt < 4; mt++) {
            const int slot = ((nt * 4 + kg) * 2 + wn) * 4 + mt;
            *(float4*)(red + slot * 128 + lane * 4) = acc[mt][nt];
        }
    __syncthreads();

    // warp (wn,kg) owns nt = kg; warp kg==0 also owns nt = 4
#pragma unroll
    for (int own = 0; own < 2; own++) {
        const int nt = (own == 0) ? kg : 4;
        if (own == 1 && kg != 0) break;

        float4 f[4];
#pragma unroll
        for (int mt = 0; mt < 4; mt++) f[mt] = make_float4(0.f, 0.f, 0.f, 0.f);
#pragma unroll
        for (int src = 0; src < 4; src++)
#pragma unroll
            for (int mt = 0; mt < 4; mt++) {
                const int slot = ((nt * 4 + src) * 2 + wn) * 4 + mt;
                const float4 v = *(const float4*)(red + slot * 128 + lane * 4);
                f[mt].x += v.x; f[mt].y += v.y; f[mt].z += v.z; f[mt].w += v.w;
            }

        const float corr = 1.00048828125f;   // 1 + 2^-11 tf32-truncation fix
        const int ch = n0 + wn * 40 + nt * 8 + 2 * j;
        if (ch < OUT_F) {
            const float2 sc = *(const float2*)(scale + ch);
            const float2 bi = *(const float2*)(bias + ch);
            const float s0 = sc.x * corr, s1 = sc.y * corr;
            const float4* bl0 = (const float4*)(Bl + (size_t)ch * RANK);
            const float4* bl1 = (const float4*)(Bl + (size_t)(ch + 1) * RANK);
            float4 bb0[4], bb1[4];
#pragma unroll
            for (int q = 0; q < 4; q++) { bb0[q] = bl0[q]; bb1[q] = bl1[q]; }

#pragma unroll
            for (int mt = 0; mt < 4; mt++) {
                const int tokA = mt * 16 + g;
                const int tokB = tokA + 8;
                float l0 = 0.f, l1 = 0.f, l0b = 0.f, l1b = 0.f;
#pragma unroll
                for (int q = 0; q < 4; q++) {
                    const float4 ta = ((const float4*)(sT + tokA * RANK))[q];
                    const float4 tb = ((const float4*)(sT + tokB * RANK))[q];
                    l0  += ta.x * bb0[q].x + ta.y * bb0[q].y + ta.z * bb0[q].z + ta.w * bb0[q].w;
                    l1  += ta.x * bb1[q].x + ta.y * bb1[q].y + ta.z * bb1[q].z + ta.w * bb1[q].w;
                    l0b += tb.x * bb0[q].x + tb.y * bb0[q].y + tb.z * bb0[q].z + tb.w * bb0[q].w;
                    l1b += tb.x * bb1[q].x + tb.y * bb1[q].y + tb.z * bb1[q].z + tb.w * bb1[q].w;
                }
                *(float2*)(out + (size_t)tokA * OUT_F + ch) =
                    make_float2(f[mt].x * s0 + l0 + bi.x, f[mt].y * s1 + l1 + bi.y);
                *(float2*)(out + (size_t)tokB * OUT_F + ch) =
                    make_float2(f[mt].z * s0 + l0b + bi.x, f[mt].w * s1 + l1b + bi.y);
            }
        }
    }
}

// ---------------------------------------------------------------------------
extern "C" void kernel_launch(void* const* d_in, const int* in_sizes, int n_in,
                              void* d_out, int out_size)
{
    const float* x     = (const float*)d_in[0];
    const float* W     = (const float*)d_in[1];
    const float* scale = (const float*)d_in[2];
    const float* A     = (const float*)d_in[3];
    const float* B     = (const float*)d_in[4];
    const float* bias  = (const float*)d_in[5];
    float* out = (float*)d_out;

    cudaFuncSetAttribute(qgemm_tf32, cudaFuncAttributeMaxDynamicSharedMemorySize, SMEM_SZ);
    prep_kernel<<<512, 256>>>(x, A);
    qgemm_tf32<<<NCTA, NTHR, SMEM_SZ>>>(W, scale, B, bias, out);
}